// round 12
// baseline (speedup 1.0000x reference)
#include <cuda_runtime.h>
#include <math.h>

#define Bsz 8
#define Tt 12
#define Hh 256
#define Ww 256
#define EC 8
#define HC 16
#define HW (Hh*Ww)

// Scratch (device globals; no allocations allowed)
__device__ float g_e1 [Bsz*Tt*EC*HW];   // encoder conv1 output (96 frames x 8ch)
__device__ float g_enc[Bsz*Tt*EC*HW];   // encoder conv2 output
__device__ float g_h[2][Bsz*HC*HW];     // ping-pong hidden state
__device__ float g_c[2][Bsz*HC*HW];     // ping-pong cell state
__device__ float g_wperm[24*9*64];      // permuted cell weights (staging for const)

// Const bank: weights [cin*9+k][gate*16 + hcg*4 + l] as ulonglong2 units,
// biases raw. Uniform-address LDC -> zero smem-crossbar traffic for weights.
__constant__ ulonglong2 c_wsv[24*9*16]; // 3456 u64x2 = 13824 floats = 54KB
__constant__ float      c_bs[64];

__device__ __forceinline__ float sigmf(float x){ return 1.0f/(1.0f+expf(-x)); }

// ---- packed f32x2 helpers (sm_100+) ----
__device__ __forceinline__ void fma2(unsigned long long& acc,
                                     unsigned long long a,
                                     unsigned long long b){
    asm("fma.rn.f32x2 %0, %1, %2, %3;" : "=l"(acc) : "l"(a), "l"(b), "l"(acc));
}
__device__ __forceinline__ unsigned long long pack2(float v){
    unsigned long long r;
    asm("mov.b64 %0, {%1, %1};" : "=l"(r) : "f"(v));
    return r;
}
__device__ __forceinline__ void unpack2(unsigned long long v, float& lo, float& hi){
    asm("mov.b64 {%0, %1}, %2;" : "=f"(lo), "=f"(hi) : "l"(v));
}

__global__ void zero_state_kernel(){
    int idx = blockIdx.x*blockDim.x + threadIdx.x;
    if (idx < Bsz*HC*HW){ g_h[0][idx]=0.f; g_c[0][idx]=0.f; }
}

// Permute cell_w [64][24][9] -> g_wperm [cin*9+k][g*16 + q*4 + l]
__global__ void permute_w_kernel(const float* __restrict__ cell_w){
    int i = blockIdx.x*blockDim.x + threadIdx.x;
    if (i >= 24*9*64) return;
    int row = i / 64;                 // cin*9 + k
    int f   = i % 64;
    int g   = f / 16;
    int rem = f % 16;
    int q   = rem / 4;                // hcg
    int l   = rem % 4;
    int cin = row / 9;
    int k   = row % 9;
    int out_ch = g*16 + q*4 + l;      // row in cell_w's 64-gate dim
    g_wperm[i] = cell_w[(out_ch*24 + cin)*9 + k];
}

// ---------------- encoder conv1: 1 -> 8, 3x3, pad 1, relu ----------------
__global__ void enc1_kernel(const float* __restrict__ x,
                            const float* __restrict__ w,
                            const float* __restrict__ b){
    __shared__ float tile[10*34];
    __shared__ float ws[72];
    __shared__ float bs[8];
    int f   = blockIdx.z;                  // frame (b*T+t), 0..95
    int tid = threadIdx.y*32 + threadIdx.x;
    if (tid < 72) ws[tid] = w[tid];
    if (tid < 8)  bs[tid] = b[tid];
    const float* xin = x + (size_t)f*HW;
    int by0 = blockIdx.y*8, bx0 = blockIdx.x*32;
    for (int i = tid; i < 340; i += 256){
        int ly = i/34, lx = i%34;
        int gy = by0 + ly - 1, gx = bx0 + lx - 1;
        float v = 0.f;
        if (gy>=0 && gy<Hh && gx>=0 && gx<Ww) v = xin[gy*Ww+gx];
        tile[i] = v;
    }
    __syncthreads();
    float acc[8];
    #pragma unroll
    for (int o=0;o<8;o++) acc[o]=bs[o];
    int base = threadIdx.y*34 + threadIdx.x;
    #pragma unroll
    for (int k=0;k<9;k++){
        float v = tile[base + (k/3)*34 + (k%3)];
        #pragma unroll
        for (int o=0;o<8;o++) acc[o] = fmaf(ws[o*9+k], v, acc[o]);
    }
    int gy = by0 + threadIdx.y, gx = bx0 + threadIdx.x;
    float* outp = g_e1 + (size_t)f*EC*HW + gy*Ww + gx;
    #pragma unroll
    for (int o=0;o<8;o++) outp[(size_t)o*HW] = fmaxf(acc[o], 0.f);
}

// ---------------- encoder conv2: 8 -> 8, 3x3, pad 1, relu ----------------
__global__ void enc2_kernel(const float* __restrict__ w,
                            const float* __restrict__ b){
    __shared__ float tile[8*10*34];                 // 2720 floats
    __shared__ __align__(16) float ws[8*9*8];       // [cin][k][o]
    __shared__ float bs[8];
    int f   = blockIdx.z;
    int tid = threadIdx.y*32 + threadIdx.x;
    for (int i=tid; i<576; i+=256){
        int o = i & 7; int k = (i>>3)%9; int cin = i/72;
        ws[i] = w[(o*8+cin)*9 + k];
    }
    if (tid<8) bs[tid] = b[tid];
    const float* in = g_e1 + (size_t)f*EC*HW;
    int by0 = blockIdx.y*8, bx0 = blockIdx.x*32;
    for (int i=tid; i<8*340; i+=256){
        int c = i/340, rem = i%340;
        int ly = rem/34, lx = rem%34;
        int gy = by0+ly-1, gx = bx0+lx-1;
        tile[i] = (gy>=0 && gy<Hh && gx>=0 && gx<Ww) ? in[(size_t)c*HW + gy*Ww+gx] : 0.f;
    }
    __syncthreads();
    float acc[8];
    #pragma unroll
    for (int o=0;o<8;o++) acc[o]=bs[o];
    int base = threadIdx.y*34 + threadIdx.x;
    #pragma unroll
    for (int cin=0;cin<8;cin++){
        #pragma unroll
        for (int k=0;k<9;k++){
            float v = tile[cin*340 + base + (k/3)*34 + (k%3)];
            const float4* wp = (const float4*)(ws + (cin*9+k)*8);
            float4 w0 = wp[0], w1 = wp[1];
            acc[0]=fmaf(w0.x,v,acc[0]); acc[1]=fmaf(w0.y,v,acc[1]);
            acc[2]=fmaf(w0.z,v,acc[2]); acc[3]=fmaf(w0.w,v,acc[3]);
            acc[4]=fmaf(w1.x,v,acc[4]); acc[5]=fmaf(w1.y,v,acc[5]);
            acc[6]=fmaf(w1.z,v,acc[6]); acc[7]=fmaf(w1.w,v,acc[7]);
        }
    }
    int gy = by0+threadIdx.y, gx = bx0+threadIdx.x;
    float* outp = g_enc + (size_t)f*EC*HW + gy*Ww + gx;
    #pragma unroll
    for (int o=0;o<8;o++) outp[(size_t)o*HW] = fmaxf(acc[o], 0.f);
}

// ---------------- ConvLSTM step: conv(cat(enc_t,h), 24 -> 64) + gates ----
// R9 structure (2 rows/thread, 256 thr, 4 blk/SM = 32 warps) with weights
// moved to the CONST BANK: uniform-address LDC replaces the 4x LDS.128 that
// made up 16 of 18 crossbar wavefronts per (cin,k). smem = tile only, 29.4KB.
__global__ __launch_bounds__(256, 4)
void lstm_step_kernel(const float* __restrict__ cell_b_unused,
                      int t, int src){
    __shared__ float tile[12*18*34];                 // 7344 floats = 29.4KB
    int bz  = blockIdx.z;
    int b   = bz >> 2, hcg = bz & 3;
    int tx  = threadIdx.x, ty = threadIdx.y;
    int tid = ty*32 + tx;

    const float* enc_t = g_enc + (size_t)((b*Tt + t)*EC)*HW;
    const float* h_src = g_h[src] + (size_t)b*HC*HW;
    int by0 = blockIdx.y*16, bx0 = blockIdx.x*32;

    // acc[j][p]: lane pair = output channels (2j, 2j+1) in o_l=(gate*4+l)
    // order: acc[2g+e] = gate g, hc pair (hcg*4+2e, hcg*4+2e+1)
    unsigned long long acc[8][2];
    #pragma unroll
    for (int j=0;j<8;j++)
        #pragma unroll
        for (int p=0;p<2;p++) acc[j][p]=0ULL;

    #pragma unroll
    for (int phase=0; phase<2; phase++){
        __syncthreads();            // wait until all reads of prior tile done
        for (int i = tid; i < 12*612; i += 256){
            int cl = i / 612, rem = i % 612;
            int ly = rem / 34, lx = rem % 34;
            int c  = cl + phase*12;
            int gy = by0 + ly - 1, gx = bx0 + lx - 1;
            float v = 0.f;
            if (gy>=0 && gy<Hh && gx>=0 && gx<Ww){
                v = (c < EC) ? enc_t[(size_t)c*HW + gy*Ww + gx]
                             : h_src[(size_t)(c-EC)*HW + gy*Ww + gx];
            }
            tile[i] = v;
        }
        __syncthreads();

        const float* tbase = tile + ty*2*34 + tx;
        #pragma unroll 1
        for (int cl=0; cl<12; cl++){
            const float* tp = tbase + cl*612;
            int row16 = ((phase*12 + cl)*9)*16;      // ulonglong2 units per row=16
            #pragma unroll
            for (int k=0;k<9;k++){
                const int r = k/3, c = k%3;
                int base = row16 + k*16 + hcg;       // uniform across threads
                ulonglong2 wA = c_wsv[base     ];    // gate0: (l0,l1),(l2,l3)
                ulonglong2 wB = c_wsv[base +  4];    // gate1
                ulonglong2 wC = c_wsv[base +  8];    // gate2
                ulonglong2 wD = c_wsv[base + 12];    // gate3
                unsigned long long vv0 = pack2(tp[(r+0)*34 + c]);
                unsigned long long vv1 = pack2(tp[(r+1)*34 + c]);
                #define STEP8(P, V) \
                    fma2(acc[0][P], V, wA.x); fma2(acc[1][P], V, wA.y); \
                    fma2(acc[2][P], V, wB.x); fma2(acc[3][P], V, wB.y); \
                    fma2(acc[4][P], V, wC.x); fma2(acc[5][P], V, wC.y); \
                    fma2(acc[6][P], V, wD.x); fma2(acc[7][P], V, wD.y);
                STEP8(0, vv0)
                STEP8(1, vv1)
                #undef STEP8
            }
        }
    }

    int gx  = bx0 + tx;
    int dst = src ^ 1;
    const float* c_src_p = g_c[src] + (size_t)b*HC*HW;
    float*       c_dst_p = g_c[dst] + (size_t)b*HC*HW;
    float*       h_dst_p = g_h[dst] + (size_t)b*HC*HW;
    #pragma unroll
    for (int p=0;p<2;p++){
        int gy = by0 + ty*2 + p;
        int pi = gy*Ww + gx;
        float g16[16];                 // [gate*4 + l]
        #pragma unroll
        for (int j=0;j<8;j++) unpack2(acc[j][p], g16[2*j], g16[2*j+1]);
        #pragma unroll
        for (int l=0;l<4;l++){
            int hc = hcg*4 + l;
            float ig = sigmf(g16[l]    + c_bs[ 0 + hc]);
            float fg = sigmf(g16[4+l]  + c_bs[16 + hc]);
            float og = sigmf(g16[8+l]  + c_bs[32 + hc]);
            float gg = tanhf(g16[12+l] + c_bs[48 + hc]);
            float cp = c_src_p[(size_t)hc*HW + pi];
            float cn = fg*cp + ig*gg;
            c_dst_p[(size_t)hc*HW + pi] = cn;
            h_dst_p[(size_t)hc*HW + pi] = og * tanhf(cn);
        }
    }
}

// ---------------- fused epilogue: mean/wp/gate/head/sigmoid --------------
__global__ void fuse_kernel(const float* __restrict__ sat, const int* __restrict__ months,
                            const float* __restrict__ wp_w, const float* __restrict__ wp_b,
                            const float* __restrict__ head_w, const float* __restrict__ head_b,
                            const float* __restrict__ sg_w1, const float* __restrict__ sg_b1,
                            const float* __restrict__ sg_w2, const float* __restrict__ sg_b2,
                            float* __restrict__ out){
    int idx = blockIdx.x*blockDim.x + threadIdx.x;
    if (idx >= Bsz*HW) return;
    int b = idx / HW, p = idx % HW;

    // scalar sat gate (1->8->1 MLP) + month prior
    float s = sat[b];
    float pre = sg_b2[0];
    #pragma unroll
    for (int j=0;j<8;j++){
        float hid = fmaxf(fmaf(sg_w1[j], s, sg_b1[j]), 0.f);
        pre = fmaf(sg_w2[j], hid, pre);
    }
    int m = months[b];
    float prior = (m>=3 && m<=6) ? 0.6f : 0.3f;
    float alpha = prior * sigmf(pre);

    // temporal mean of encoder features
    float feat[8];
    #pragma unroll
    for (int c=0;c<8;c++){
        float a = 0.f;
        #pragma unroll
        for (int t=0;t<Tt;t++) a += g_enc[(size_t)((b*Tt+t)*EC+c)*HW + p];
        feat[c] = a * (1.0f/12.0f);
    }

    // wp 1x1 conv + fuse + head 1x1 conv + sigmoid
    float res = head_b[0];
    #pragma unroll
    for (int hc=0; hc<16; hc++){
        float haux = wp_b[hc];
        #pragma unroll
        for (int c=0;c<8;c++) haux = fmaf(wp_w[hc*8+c], feat[c], haux);
        float hm = g_h[0][(size_t)(b*HC+hc)*HW + p];   // after 12 steps h lives in buf 0
        res = fmaf(head_w[hc], hm + alpha*haux, res);
    }
    out[idx] = sigmf(res);
}

extern "C" void kernel_launch(void* const* d_in, const int* in_sizes, int n_in,
                              void* d_out, int out_size){
    const float* x       = (const float*)d_in[0];
    const float* sat     = (const float*)d_in[1];
    const int*   months  = (const int*)  d_in[2];
    const float* enc_w1  = (const float*)d_in[3];
    const float* enc_b1  = (const float*)d_in[4];
    const float* enc_w2  = (const float*)d_in[5];
    const float* enc_b2  = (const float*)d_in[6];
    const float* cell_w  = (const float*)d_in[7];
    const float* cell_b  = (const float*)d_in[8];
    const float* wp_w    = (const float*)d_in[9];
    const float* wp_b    = (const float*)d_in[10];
    const float* head_w  = (const float*)d_in[11];
    const float* head_b  = (const float*)d_in[12];
    const float* sg_w1   = (const float*)d_in[13];
    const float* sg_b1   = (const float*)d_in[14];
    const float* sg_w2   = (const float*)d_in[15];
    const float* sg_b2   = (const float*)d_in[16];
    float* out = (float*)d_out;

    dim3 blk256(32, 8);
    zero_state_kernel<<<(Bsz*HC*HW + 255)/256, 256>>>();
    enc1_kernel<<<dim3(8, 32, Bsz*Tt), blk256>>>(x, enc_w1, enc_b1);
    enc2_kernel<<<dim3(8, 32, Bsz*Tt), blk256>>>(enc_w2, enc_b2);

    // stage permuted weights + biases into the const bank (async d2d; capture-safe)
    permute_w_kernel<<<(24*9*64 + 255)/256, 256>>>(cell_w);
    void* wperm_addr = nullptr;
    cudaGetSymbolAddress(&wperm_addr, g_wperm);
    cudaMemcpyToSymbolAsync(c_wsv, wperm_addr, 24*9*64*sizeof(float), 0,
                            cudaMemcpyDeviceToDevice);
    cudaMemcpyToSymbolAsync(c_bs, cell_b, 64*sizeof(float), 0,
                            cudaMemcpyDeviceToDevice);

    for (int t=0; t<Tt; t++){
        // src parity: t even reads buf0, writes buf1; final h lands in buf0
        lstm_step_kernel<<<dim3(8, 16, Bsz*4), dim3(32,8)>>>(cell_b, t, t & 1);
    }
    fuse_kernel<<<(Bsz*HW + 255)/256, 256>>>(sat, months, wp_w, wp_b,
                                             head_w, head_b, sg_w1, sg_b1,
                                             sg_w2, sg_b2, out);
}

// round 13
// speedup vs baseline: 1.2964x; 1.2964x over previous
#include <cuda_runtime.h>
#include <math.h>

#define Bsz 8
#define Tt 12
#define Hh 256
#define Ww 256
#define EC 8
#define HC 16
#define HW (Hh*Ww)

// Scratch (device globals; no allocations allowed)
__device__ float g_e1 [Bsz*Tt*EC*HW];   // encoder conv1 output (96 frames x 8ch)
__device__ float g_enc[Bsz*Tt*EC*HW];   // encoder conv2 output
__device__ float g_h[2][Bsz*HC*HW];     // ping-pong hidden state
__device__ float g_c[2][Bsz*HC*HW];     // ping-pong cell state

__device__ __forceinline__ float sigmf(float x){ return 1.0f/(1.0f+expf(-x)); }

// ---- packed f32x2 helpers (sm_100+) ----
__device__ __forceinline__ void fma2(unsigned long long& acc,
                                     unsigned long long a,
                                     unsigned long long b){
    asm("fma.rn.f32x2 %0, %1, %2, %3;" : "=l"(acc) : "l"(a), "l"(b), "l"(acc));
}
__device__ __forceinline__ unsigned long long pack2(float v){
    unsigned long long r;
    asm("mov.b64 %0, {%1, %1};" : "=l"(r) : "f"(v));
    return r;
}
__device__ __forceinline__ void unpack2(unsigned long long v, float& lo, float& hi){
    asm("mov.b64 {%0, %1}, %2;" : "=f"(lo), "=f"(hi) : "l"(v));
}

__global__ void zero_state_kernel(){
    int idx = blockIdx.x*blockDim.x + threadIdx.x;
    if (idx < Bsz*HC*HW){ g_h[0][idx]=0.f; g_c[0][idx]=0.f; }
}

// ---------------- encoder conv1: 1 -> 8, 3x3, pad 1, relu ----------------
__global__ void enc1_kernel(const float* __restrict__ x,
                            const float* __restrict__ w,
                            const float* __restrict__ b){
    __shared__ float tile[10*34];
    __shared__ float ws[72];
    __shared__ float bs[8];
    int f   = blockIdx.z;                  // frame (b*T+t), 0..95
    int tid = threadIdx.y*32 + threadIdx.x;
    if (tid < 72) ws[tid] = w[tid];
    if (tid < 8)  bs[tid] = b[tid];
    const float* xin = x + (size_t)f*HW;
    int by0 = blockIdx.y*8, bx0 = blockIdx.x*32;
    for (int i = tid; i < 340; i += 256){
        int ly = i/34, lx = i%34;
        int gy = by0 + ly - 1, gx = bx0 + lx - 1;
        float v = 0.f;
        if (gy>=0 && gy<Hh && gx>=0 && gx<Ww) v = xin[gy*Ww+gx];
        tile[i] = v;
    }
    __syncthreads();
    float acc[8];
    #pragma unroll
    for (int o=0;o<8;o++) acc[o]=bs[o];
    int base = threadIdx.y*34 + threadIdx.x;
    #pragma unroll
    for (int k=0;k<9;k++){
        float v = tile[base + (k/3)*34 + (k%3)];
        #pragma unroll
        for (int o=0;o<8;o++) acc[o] = fmaf(ws[o*9+k], v, acc[o]);
    }
    int gy = by0 + threadIdx.y, gx = bx0 + threadIdx.x;
    float* outp = g_e1 + (size_t)f*EC*HW + gy*Ww + gx;
    #pragma unroll
    for (int o=0;o<8;o++) outp[(size_t)o*HW] = fmaxf(acc[o], 0.f);
}

// ---------------- encoder conv2: 8 -> 8, 3x3, pad 1, relu ----------------
// R9-style: 2 rows/thread, f32x2 over the 8 output channels (4 u64 acc/row).
__global__ __launch_bounds__(256, 4)
void enc2_kernel(const float* __restrict__ w,
                 const float* __restrict__ b){
    __shared__ float tile[8*18*34];                 // 4896 floats = 19.6KB
    __shared__ __align__(16) float ws[8*9*8];       // [cin][k][o]
    __shared__ float bs[8];
    int f   = blockIdx.z;
    int tx  = threadIdx.x, ty = threadIdx.y;
    int tid = ty*32 + tx;
    for (int i=tid; i<576; i+=256){
        int o = i & 7; int k = (i>>3)%9; int cin = i/72;
        ws[i] = w[(o*8+cin)*9 + k];
    }
    if (tid<8) bs[tid] = b[tid];
    const float* in = g_e1 + (size_t)f*EC*HW;
    int by0 = blockIdx.y*16, bx0 = blockIdx.x*32;
    for (int i=tid; i<8*612; i+=256){
        int c = i/612, rem = i%612;
        int ly = rem/34, lx = rem%34;
        int gy = by0+ly-1, gx = bx0+lx-1;
        tile[i] = (gy>=0 && gy<Hh && gx>=0 && gx<Ww) ? in[(size_t)c*HW + gy*Ww+gx] : 0.f;
    }
    __syncthreads();

    unsigned long long acc[4][2];
    #pragma unroll
    for (int j=0;j<4;j++){ acc[j][0]=0ULL; acc[j][1]=0ULL; }

    const float* tbase = tile + ty*2*34 + tx;
    const ulonglong2* wsv = (const ulonglong2*)ws;
    #pragma unroll 1
    for (int cin=0;cin<8;cin++){
        const float* tp = tbase + cin*612;
        #pragma unroll
        for (int k=0;k<9;k++){
            const int r = k/3, c = k%3;
            ulonglong2 wA = wsv[(cin*9+k)*2+0];   // pairs (o0,o1),(o2,o3)
            ulonglong2 wB = wsv[(cin*9+k)*2+1];   // pairs (o4,o5),(o6,o7)
            unsigned long long vv0 = pack2(tp[(r+0)*34 + c]);
            unsigned long long vv1 = pack2(tp[(r+1)*34 + c]);
            fma2(acc[0][0],vv0,wA.x); fma2(acc[1][0],vv0,wA.y);
            fma2(acc[2][0],vv0,wB.x); fma2(acc[3][0],vv0,wB.y);
            fma2(acc[0][1],vv1,wA.x); fma2(acc[1][1],vv1,wA.y);
            fma2(acc[2][1],vv1,wB.x); fma2(acc[3][1],vv1,wB.y);
        }
    }
    int gx = bx0 + tx;
    #pragma unroll
    for (int p=0;p<2;p++){
        int gy = by0 + ty*2 + p;
        float o8[8];
        #pragma unroll
        for (int j=0;j<4;j++) unpack2(acc[j][p], o8[2*j], o8[2*j+1]);
        float* outp = g_enc + (size_t)f*EC*HW + gy*Ww + gx;
        #pragma unroll
        for (int o=0;o<8;o++) outp[(size_t)o*HW] = fmaxf(o8[o]+bs[o], 0.f);
    }
}

// ---------------- ConvLSTM step: conv(cat(enc_t,h), 24 -> 64) + gates ----
// R9 kernel verbatim, templated on FIRST: at t=0, h=c=0 so channels 8-23
// contribute exactly zero -> 1 phase x 8 channels, and cn = ig*gg (no c read).
template<bool FIRST>
__global__ __launch_bounds__(256, 4)
void lstm_step_kernel(const float* __restrict__ cell_w,
                      const float* __restrict__ cell_b,
                      int t, int src){
    __shared__ float tile[12*18*34];                 // 7344 floats = 29.4KB
    __shared__ __align__(16) float ws[24*9*16];      // [cin][k][o_l], 13.8KB
    __shared__ float bs[16];
    int bz  = blockIdx.z;
    int b   = bz >> 2, hcg = bz & 3;
    int tx  = threadIdx.x, ty = threadIdx.y;
    int tid = ty*32 + tx;

    const int WLIM = FIRST ? 8*144 : 3456;
    for (int i = tid; i < WLIM; i += 256){
        int o_l = i & 15;
        int k   = (i >> 4) % 9;
        int cin = i / 144;
        int row = (o_l>>2)*16 + hcg*4 + (o_l&3);     // gate*16 + hc
        ws[i] = cell_w[(row*24 + cin)*9 + k];
    }
    if (tid < 16) bs[tid] = cell_b[(tid>>2)*16 + hcg*4 + (tid&3)];

    const float* enc_t = g_enc + (size_t)((b*Tt + t)*EC)*HW;
    const float* h_src = g_h[src] + (size_t)b*HC*HW;
    int by0 = blockIdx.y*16, bx0 = blockIdx.x*32;

    // acc[j][p]: lane pair = output channels (2j, 2j+1), p = pixel row 0..1
    unsigned long long acc[8][2];
    #pragma unroll
    for (int j=0;j<8;j++)
        #pragma unroll
        for (int p=0;p<2;p++) acc[j][p]=0ULL;

    const int NPH = FIRST ? 1 : 2;
    const int CPP = FIRST ? 8 : 12;
    #pragma unroll
    for (int phase=0; phase<NPH; phase++){
        __syncthreads();            // wait until all reads of prior tile done
        for (int i = tid; i < CPP*612; i += 256){
            int cl = i / 612, rem = i % 612;
            int ly = rem / 34, lx = rem % 34;
            int c  = cl + phase*12;
            int gy = by0 + ly - 1, gx = bx0 + lx - 1;
            float v = 0.f;
            if (gy>=0 && gy<Hh && gx>=0 && gx<Ww){
                v = (c < EC) ? enc_t[(size_t)c*HW + gy*Ww + gx]
                             : h_src[(size_t)(c-EC)*HW + gy*Ww + gx];
            }
            tile[i] = v;
        }
        __syncthreads();

        const float* tbase = tile + ty*2*34 + tx;
        #pragma unroll 1
        for (int cl=0; cl<CPP; cl++){
            const float*      tp = tbase + cl*612;
            const ulonglong2* wp = (const ulonglong2*)(ws + (size_t)(phase*12 + cl)*144);
            #pragma unroll
            for (int k=0;k<9;k++){
                const int r = k/3, c = k%3;
                ulonglong2 wA = wp[k*4+0];   // pairs (o0,o1),(o2,o3)
                ulonglong2 wB = wp[k*4+1];   // pairs (o4,o5),(o6,o7)
                ulonglong2 wC = wp[k*4+2];   // pairs (o8,o9),(o10,o11)
                ulonglong2 wD = wp[k*4+3];   // pairs (o12,o13),(o14,o15)
                unsigned long long vv0 = pack2(tp[(r+0)*34 + c]);
                unsigned long long vv1 = pack2(tp[(r+1)*34 + c]);
                #define STEP8(P, V) \
                    fma2(acc[0][P], V, wA.x); fma2(acc[1][P], V, wA.y); \
                    fma2(acc[2][P], V, wB.x); fma2(acc[3][P], V, wB.y); \
                    fma2(acc[4][P], V, wC.x); fma2(acc[5][P], V, wC.y); \
                    fma2(acc[6][P], V, wD.x); fma2(acc[7][P], V, wD.y);
                STEP8(0, vv0)
                STEP8(1, vv1)
                #undef STEP8
            }
        }
    }

    int gx  = bx0 + tx;
    int dst = src ^ 1;
    const float* c_src_p = g_c[src] + (size_t)b*HC*HW;
    float*       c_dst_p = g_c[dst] + (size_t)b*HC*HW;
    float*       h_dst_p = g_h[dst] + (size_t)b*HC*HW;
    #pragma unroll
    for (int p=0;p<2;p++){
        int gy = by0 + ty*2 + p;
        int pi = gy*Ww + gx;
        float g16[16];
        #pragma unroll
        for (int j=0;j<8;j++) unpack2(acc[j][p], g16[2*j], g16[2*j+1]);
        #pragma unroll
        for (int l=0;l<4;l++){
            int hc = hcg*4 + l;
            float ig = sigmf(g16[l]    + bs[l]);
            float og = sigmf(g16[8+l]  + bs[8+l]);
            float gg = tanhf(g16[12+l] + bs[12+l]);
            float cn;
            if (FIRST){
                cn = ig*gg;                       // f*c0 = 0 exactly
            } else {
                float fg = sigmf(g16[4+l]  + bs[4+l]);
                float cp = c_src_p[(size_t)hc*HW + pi];
                cn = fg*cp + ig*gg;
            }
            c_dst_p[(size_t)hc*HW + pi] = cn;
            h_dst_p[(size_t)hc*HW + pi] = og * tanhf(cn);
        }
    }
}

// ---------------- fused epilogue: mean/wp/gate/head/sigmoid --------------
__global__ void fuse_kernel(const float* __restrict__ sat, const int* __restrict__ months,
                            const float* __restrict__ wp_w, const float* __restrict__ wp_b,
                            const float* __restrict__ head_w, const float* __restrict__ head_b,
                            const float* __restrict__ sg_w1, const float* __restrict__ sg_b1,
                            const float* __restrict__ sg_w2, const float* __restrict__ sg_b2,
                            float* __restrict__ out){
    int idx = blockIdx.x*blockDim.x + threadIdx.x;
    if (idx >= Bsz*HW) return;
    int b = idx / HW, p = idx % HW;

    // scalar sat gate (1->8->1 MLP) + month prior
    float s = sat[b];
    float pre = sg_b2[0];
    #pragma unroll
    for (int j=0;j<8;j++){
        float hid = fmaxf(fmaf(sg_w1[j], s, sg_b1[j]), 0.f);
        pre = fmaf(sg_w2[j], hid, pre);
    }
    int m = months[b];
    float prior = (m>=3 && m<=6) ? 0.6f : 0.3f;
    float alpha = prior * sigmf(pre);

    // temporal mean of encoder features
    float feat[8];
    #pragma unroll
    for (int c=0;c<8;c++){
        float a = 0.f;
        #pragma unroll
        for (int t=0;t<Tt;t++) a += g_enc[(size_t)((b*Tt+t)*EC+c)*HW + p];
        feat[c] = a * (1.0f/12.0f);
    }

    // wp 1x1 conv + fuse + head 1x1 conv + sigmoid
    float res = head_b[0];
    #pragma unroll
    for (int hc=0; hc<16; hc++){
        float haux = wp_b[hc];
        #pragma unroll
        for (int c=0;c<8;c++) haux = fmaf(wp_w[hc*8+c], feat[c], haux);
        float hm = g_h[0][(size_t)(b*HC+hc)*HW + p];   // after 12 steps h lives in buf 0
        res = fmaf(head_w[hc], hm + alpha*haux, res);
    }
    out[idx] = sigmf(res);
}

extern "C" void kernel_launch(void* const* d_in, const int* in_sizes, int n_in,
                              void* d_out, int out_size){
    const float* x       = (const float*)d_in[0];
    const float* sat     = (const float*)d_in[1];
    const int*   months  = (const int*)  d_in[2];
    const float* enc_w1  = (const float*)d_in[3];
    const float* enc_b1  = (const float*)d_in[4];
    const float* enc_w2  = (const float*)d_in[5];
    const float* enc_b2  = (const float*)d_in[6];
    const float* cell_w  = (const float*)d_in[7];
    const float* cell_b  = (const float*)d_in[8];
    const float* wp_w    = (const float*)d_in[9];
    const float* wp_b    = (const float*)d_in[10];
    const float* head_w  = (const float*)d_in[11];
    const float* head_b  = (const float*)d_in[12];
    const float* sg_w1   = (const float*)d_in[13];
    const float* sg_b1   = (const float*)d_in[14];
    const float* sg_w2   = (const float*)d_in[15];
    const float* sg_b2   = (const float*)d_in[16];
    float* out = (float*)d_out;

    dim3 blk256(32, 8);
    // NB: zero_state only needed for buffers feeding non-FIRST steps via parity;
    // keep it for safety (t=1 reads g_h[1]/g_c[1] which FIRST writes; g_h[0] end).
    zero_state_kernel<<<(Bsz*HC*HW + 255)/256, 256>>>();
    enc1_kernel<<<dim3(8, 32, Bsz*Tt), blk256>>>(x, enc_w1, enc_b1);
    enc2_kernel<<<dim3(8, 16, Bsz*Tt), blk256>>>(enc_w2, enc_b2);
    // t=0: h=c=0 -> specialized kernel (8 input channels, no c read)
    lstm_step_kernel<true><<<dim3(8, 16, Bsz*4), blk256>>>(cell_w, cell_b, 0, 0);
    for (int t=1; t<Tt; t++){
        // src parity: t even reads buf0, writes buf1; final h lands in buf0
        lstm_step_kernel<false><<<dim3(8, 16, Bsz*4), blk256>>>(cell_w, cell_b, t, t & 1);
    }
    fuse_kernel<<<(Bsz*HW + 255)/256, 256>>>(sat, months, wp_w, wp_b,
                                             head_w, head_b, sg_w1, sg_b1,
                                             sg_w2, sg_b2, out);
}